// round 2
// baseline (speedup 1.0000x reference)
#include <cuda_runtime.h>
#include <math.h>

namespace {
constexpr int H    = 16;
constexpr int C    = 32;
constexpr int HID  = 512;
constexpr int HP   = 32;     // hidden per holiday
constexpr int SKUD = 64;
constexpr int ROWS = 32;     // batch rows per CTA
constexpr int NTHR = 256;
constexpr int KT   = 16;     // k-tile for staged GEMMs
constexpr int XS   = 513;    // padded X stride (bank-conflict-free)

constexpr float TEMP_INV = 1.0f / 0.7f;
constexpr float TMAX     = 365.0f;
constexpr float LN_EPS   = 1e-3f;

// shared memory layout (in floats)
constexpr int OFF_X    = 0;                       // X buffer: aggregated then H1  (32*513)
constexpr int OFF_WT   = OFF_X    + ROWS * XS;    // W k-tile (16*512)
constexpr int OFF_A    = OFF_WT   + KT * HID;     // union: Wh (16*32*32) then beta (32*512)
constexpr int OFF_SKU  = OFF_A    + H * C * HP;   // sku tile 32*64
constexpr int OFF_CPS  = OFF_SKU  + ROWS * SKUD;  // 512
constexpr int OFF_G    = OFF_CPS  + H * C;        // 512
constexpr int OFF_B    = OFF_G    + H * C;        // 512
constexpr int OFF_WO   = OFF_B    + H * C;        // 512
constexpr int OFF_WAWO = OFF_WO   + HID;          // 64
constexpr int OFF_AW   = OFF_WAWO + SKUD;         // 16
constexpr int SMEM_FLOATS = OFF_AW + H;           // 45168
constexpr int SMEM_BYTES  = SMEM_FLOATS * 4;      // 180672 B
}

__device__ __forceinline__ float mishf(float x) {
    float sp = (x > 20.f) ? x : log1pf(expf(x));
    return x * tanhf(sp);
}

// Register-tiled GEMM: acc[4][16] += X[r0..r0+3][k] * W[k][tx+32j], k in [0,ktot)
// W streamed from global through the shared k-tile. All threads must call
// (contains __syncthreads).
__device__ __forceinline__ void gemm_acc(
    const float* __restrict__ gW, int ktot,
    const float* xb, int xstride, int r0,
    float* sWt, float acc[4][16], int tid, int tx)
{
#pragma unroll
    for (int i = 0; i < 4; i++)
#pragma unroll
        for (int j = 0; j < 16; j++) acc[i][j] = 0.f;

    for (int kt = 0; kt < ktot; kt += KT) {
        __syncthreads();
        // stage W[kt..kt+15][0..511] -> shared (8192 floats, 8 float4 / thread)
        const float4* src = reinterpret_cast<const float4*>(gW + kt * HID);
        float4*       dst = reinterpret_cast<float4*>(sWt);
#pragma unroll
        for (int i = 0; i < (KT * HID / 4) / NTHR; i++)
            dst[tid + i * NTHR] = src[tid + i * NTHR];
        __syncthreads();

#pragma unroll
        for (int kk = 0; kk < KT; kk++) {
            float xv[4];
#pragma unroll
            for (int i = 0; i < 4; i++)
                xv[i] = xb[(r0 + i) * xstride + kt + kk];   // warp-broadcast
#pragma unroll
            for (int j = 0; j < 16; j++) {
                float wv = sWt[kk * HID + tx + 32 * j];      // conflict-free
#pragma unroll
                for (int i = 0; i < 4; i++)
                    acc[i][j] = fmaf(xv[i], wv, acc[i][j]);
            }
        }
    }
}

__global__ __launch_bounds__(NTHR)
void holiday_fused_kernel(
    const float* __restrict__ inputs,     // [B,16]
    const float* __restrict__ sku,        // [B,64]
    const float* __restrict__ deltas,     // [16,32]
    const float* __restrict__ ln_gamma,   // [16,32]
    const float* __restrict__ ln_beta,    // [16,32]
    const float* __restrict__ attn_w,     // [16]
    const float* __restrict__ Wh,         // [16,32,32]
    const float* __restrict__ Wah,        // [512,512]
    const float* __restrict__ Waa,        // [512,512]
    const float* __restrict__ Wb,         // [64,512]
    const float* __restrict__ Wa,         // [64,512]
    const float* __restrict__ Wo,         // [512,1]
    float* __restrict__ out)              // [B]
{
    extern __shared__ float sm[];
    float* sX    = sm + OFF_X;
    float* sWt   = sm + OFF_WT;
    float* sA    = sm + OFF_A;     // Wh, later beta
    float* sSku  = sm + OFF_SKU;
    float* sCps  = sm + OFF_CPS;
    float* sG    = sm + OFF_G;
    float* sBl   = sm + OFF_B;
    float* sWo   = sm + OFF_WO;
    float* sWaWo = sm + OFF_WAWO;
    float* sAw   = sm + OFF_AW;

    const int tid = threadIdx.x;
    const int tx  = tid & 31;
    const int wid = tid >> 5;
    const int r0  = wid * 4;            // 4 output rows per warp
    const int b0  = blockIdx.x * ROWS;

    // ---------------- stage 0: load constants -------------------------------
    for (int i = tid; i < H * C; i += NTHR) { sG[i] = ln_gamma[i]; sBl[i] = ln_beta[i]; }
    for (int i = tid; i < HID;  i += NTHR) sWo[i] = Wo[i];
    if (tid < H) sAw[tid] = attn_w[tid] * TEMP_INV;
    {   // Wh -> shared (16384 floats)
        const float4* s4 = reinterpret_cast<const float4*>(Wh);
        float4*       d4 = reinterpret_cast<float4*>(sA);
#pragma unroll
        for (int i = 0; i < (H * C * HP / 4) / NTHR; i++)
            d4[tid + i * NTHR] = s4[tid + i * NTHR];
    }
    {   // sku tile (rows are contiguous)
        const float4* s4 = reinterpret_cast<const float4*>(sku + (size_t)b0 * SKUD);
        float4*       d4 = reinterpret_cast<float4*>(sSku);
#pragma unroll
        for (int i = 0; i < (ROWS * SKUD / 4) / NTHR; i++)
            d4[tid + i * NTHR] = s4[tid + i * NTHR];
    }
    if (tid < H) {   // changepoints: softplus -> cumsum -> rescale to [0,365]
        float cum = 0.f, tmp[C];
#pragma unroll
        for (int c = 0; c < C; c++) {
            float x  = deltas[tid * C + c];
            float sp = (x > 20.f) ? x : log1pf(expf(x));
            cum += sp;  tmp[c] = cum;
        }
        float sc = TMAX / cum;
#pragma unroll
        for (int c = 0; c < C; c++) sCps[tid * C + c] = tmp[c] * sc;
    }
    __syncthreads();

    // WaWo[s] = Wa[s,:] . Wo  (alpha term factored through the final dot)
    {   // warp w handles s = w*8 .. w*8+7
#pragma unroll
        for (int si = 0; si < SKUD / 8; si++) {
            int s = wid * 8 + si;
            float p = 0.f;
#pragma unroll
            for (int j = 0; j < 16; j++) {
                int c = tx + 32 * j;
                p = fmaf(Wa[s * HID + c], sWo[c], p);
            }
#pragma unroll
            for (int o = 16; o > 0; o >>= 1) p += __shfl_xor_sync(0xffffffffu, p, o);
            if (tx == 0) sWaWo[s] = p;
        }
    }

    // ---------------- stage 1: per-(row,holiday) features -> aggregated -----
#pragma unroll
    for (int tt = 0; tt < 2; tt++) {
        int task = tid + tt * NTHR;          // 512 tasks
        int h = task >> 5;                   // warp-uniform
        int r = task & 31;
        float t = inputs[(b0 + r) * H + h];
        float f[C], e[C];
        float mu = 0.f;
#pragma unroll
        for (int c = 0; c < C; c++) { f[c] = fmaxf(t - sCps[h * C + c], 0.f); mu += f[c]; }
        mu *= (1.0f / C);
        float var = 0.f;
#pragma unroll
        for (int c = 0; c < C; c++) { float d = f[c] - mu; var = fmaf(d, d, var); }
        var *= (1.0f / C);
        float rs = rsqrtf(var + LN_EPS);
        float aw = sAw[h];
        float m = -3.4e38f;
#pragma unroll
        for (int c = 0; c < C; c++) {
            float n = fmaf((f[c] - mu) * rs, sG[h * C + c], sBl[h * C + c]);
            f[c] = n;
            float l = n * aw;
            e[c] = l;  m = fmaxf(m, l);
        }
        float s = 0.f;
#pragma unroll
        for (int c = 0; c < C; c++) { e[c] = expf(e[c] - m); s += e[c]; }
        float inv = 1.0f / s;
#pragma unroll
        for (int c = 0; c < C; c++) f[c] *= e[c] * inv;   // attended
        float hid[HP];
#pragma unroll
        for (int d = 0; d < HP; d++) hid[d] = 0.f;
#pragma unroll
        for (int c = 0; c < C; c++) {
            float a = f[c];
#pragma unroll
            for (int d = 0; d < HP; d++)
                hid[d] = fmaf(a, sA[(h * C + c) * HP + d], hid[d]);  // sA==Wh here
        }
#pragma unroll
        for (int d = 0; d < HP; d++)
            sX[r * XS + h * HP + d] = mishf(hid[d]);
    }

    float acc[4][16];

    // ---------------- stage 2a: beta = sigmoid(sku @ Wb) --------------------
    gemm_acc(Wb, SKUD, sSku, SKUD, r0, sWt, acc, tid, tx);
    // writing into sA (overwrites Wh — all Wh readers passed the gemm barriers)
#pragma unroll
    for (int i = 0; i < 4; i++)
#pragma unroll
        for (int j = 0; j < 16; j++)
            sA[(r0 + i) * HID + tx + 32 * j] = 1.0f / (1.0f + expf(-acc[i][j]));

    // ---------------- stage 2b: H1 = mish(X @ Wah) --------------------------
    gemm_acc(Wah, HID, sX, XS, r0, sWt, acc, tid, tx);
    __syncthreads();                        // everyone done reading old sX
#pragma unroll
    for (int i = 0; i < 4; i++)
#pragma unroll
        for (int j = 0; j < 16; j++)
            sX[(r0 + i) * XS + tx + 32 * j] = mishf(acc[i][j]);

    // ---------------- stage 3: logits = H1 @ Waa ----------------------------
    gemm_acc(Waa, HID, sX, XS, r0, sWt, acc, tid, tx);

    // ---------------- epilogue: softmax, *H1, *beta, +alpha, @Wo ------------
#pragma unroll
    for (int i = 0; i < 4; i++) {
        int r = r0 + i;
        float l[16];
        float m = -3.4e38f;
#pragma unroll
        for (int j = 0; j < 16; j++) { l[j] = acc[i][j] * TEMP_INV; m = fmaxf(m, l[j]); }
#pragma unroll
        for (int o = 16; o > 0; o >>= 1) m = fmaxf(m, __shfl_xor_sync(0xffffffffu, m, o));
        float s = 0.f;
#pragma unroll
        for (int j = 0; j < 16; j++) { l[j] = expf(l[j] - m); s += l[j]; }
#pragma unroll
        for (int o = 16; o > 0; o >>= 1) s += __shfl_xor_sync(0xffffffffu, s, o);
        float inv = 1.0f / s;
        // alpha contribution: sku[r] . (Wa@Wo), distributed over lanes
        float p = fmaf(sSku[r * SKUD + tx],      sWaWo[tx],
                  sSku[r * SKUD + tx + 32] * sWaWo[tx + 32]);
#pragma unroll
        for (int j = 0; j < 16; j++) {
            int c = tx + 32 * j;
            float h1 = sX[r * XS + c];
            float bt = sA[r * HID + c];
            p = fmaf(h1 * (l[j] * inv) * bt, sWo[c], p);
        }
#pragma unroll
        for (int o = 16; o > 0; o >>= 1) p += __shfl_xor_sync(0xffffffffu, p, o);
        if (tx == 0) out[b0 + r] = p;
    }
}

extern "C" void kernel_launch(void* const* d_in, const int* in_sizes, int n_in,
                              void* d_out, int out_size)
{
    const float* inputs   = (const float*)d_in[0];
    const float* sku      = (const float*)d_in[1];
    const float* deltas   = (const float*)d_in[2];
    const float* ln_gamma = (const float*)d_in[3];
    const float* ln_beta  = (const float*)d_in[4];
    const float* attn_w   = (const float*)d_in[5];
    const float* Wh       = (const float*)d_in[6];
    const float* Wah      = (const float*)d_in[7];
    const float* Waa      = (const float*)d_in[8];
    const float* Wb       = (const float*)d_in[9];
    const float* Wa       = (const float*)d_in[10];
    const float* Wo       = (const float*)d_in[11];
    float* out = (float*)d_out;

    int B = in_sizes[0] / H;
    cudaFuncSetAttribute(holiday_fused_kernel,
                         cudaFuncAttributeMaxDynamicSharedMemorySize, SMEM_BYTES);
    holiday_fused_kernel<<<B / ROWS, NTHR, SMEM_BYTES>>>(
        inputs, sku, deltas, ln_gamma, ln_beta, attn_w,
        Wh, Wah, Waa, Wb, Wa, Wo, out);
}

// round 3
// speedup vs baseline: 1.4610x; 1.4610x over previous
#include <cuda_runtime.h>
#include <cuda_fp16.h>
#include <math.h>

namespace {
constexpr int H    = 16;
constexpr int C    = 32;
constexpr int HID  = 512;
constexpr int SKUD = 64;
constexpr int ROWS = 32;     // batch rows per CTA
constexpr int NTHR = 256;
constexpr int KT   = 8;      // k-tile for staged GEMMs
constexpr int XS   = 514;    // padded X stride (even for float2, low-conflict)

constexpr float TEMP_INV = 1.0f / 0.7f;
constexpr float TMAX     = 365.0f;
constexpr float LN_EPS   = 1e-3f;

// shared memory layout (floats)
constexpr int OFF_X    = 0;                      // 32*514 = 16448  (aggregated, then H1)
constexpr int OFF_WT   = OFF_X  + ROWS * XS;     // 8*512  = 4096   (W k-tile)
constexpr int OFF_BETA = OFF_WT + KT * HID;      // 8192 float-slots = 16384 halves
constexpr int OFF_WAWO = OFF_BETA + 8192;        // 64
constexpr int SMEM_FLOATS = OFF_WAWO + SKUD;     // 28800
constexpr int SMEM_BYTES  = SMEM_FLOATS * 4;     // 115200 B  (fits 2 CTAs/SM)
}

using ull = unsigned long long;

__device__ __forceinline__ ull pack2(float x, float y) {
    ull r; asm("mov.b64 %0, {%1, %2};" : "=l"(r) : "f"(x), "f"(y)); return r;
}
__device__ __forceinline__ float2 unpack2(ull v) {
    float2 f; asm("mov.b64 {%0, %1}, %2;" : "=f"(f.x), "=f"(f.y) : "l"(v)); return f;
}
__device__ __forceinline__ void ffma2(ull& d, ull a, ull b) {
    asm("fma.rn.f32x2 %0, %1, %2, %0;" : "+l"(d) : "l"(a), "l"(b));
}
__device__ __forceinline__ float mishf(float x) {
    float sp = (x > 20.f) ? x : log1pf(expf(x));
    return x * tanhf(sp);
}

// Register-tiled packed GEMM: acc2[i][j] holds C[r0+i][2tx+64j .. +1].
// W streamed from global through the shared k-tile. All threads must call.
__device__ __forceinline__ void gemm_acc2(
    const float* __restrict__ gW, int ktot,
    const float* __restrict__ xb, int xstride, int r0,
    float* sWt, ull acc[4][8], int tid, int tx)
{
#pragma unroll
    for (int i = 0; i < 4; i++)
#pragma unroll
        for (int j = 0; j < 8; j++) acc[i][j] = 0ull;

    for (int kt = 0; kt < ktot; kt += KT) {
        __syncthreads();
        const float4* src = reinterpret_cast<const float4*>(gW + (size_t)kt * HID);
        float4*       dst = reinterpret_cast<float4*>(sWt);
#pragma unroll
        for (int i = 0; i < (KT * HID / 4) / NTHR; i++)
            dst[tid + i * NTHR] = src[tid + i * NTHR];
        __syncthreads();

#pragma unroll
        for (int kk = 0; kk < KT; kk++) {
            ull xv2[4];
#pragma unroll
            for (int i = 0; i < 4; i++) {
                float x = xb[(size_t)(r0 + i) * xstride + kt + kk];  // broadcast
                xv2[i] = pack2(x, x);
            }
#pragma unroll
            for (int j = 0; j < 8; j++) {
                ull w2 = *reinterpret_cast<const ull*>(sWt + kk * HID + 2 * tx + 64 * j);
#pragma unroll
                for (int i = 0; i < 4; i++)
                    ffma2(acc[i][j], xv2[i], w2);
            }
        }
    }
}

__global__ __launch_bounds__(NTHR, 2)
void holiday_fused_kernel(
    const float* __restrict__ inputs,     // [B,16]
    const float* __restrict__ sku,        // [B,64]
    const float* __restrict__ deltas,     // [16,32]
    const float* __restrict__ ln_gamma,   // [16,32]
    const float* __restrict__ ln_beta,    // [16,32]
    const float* __restrict__ attn_w,     // [16]
    const float* __restrict__ Wh,         // [16,32,32]
    const float* __restrict__ Wah,        // [512,512]
    const float* __restrict__ Waa,        // [512,512]
    const float* __restrict__ Wb,         // [64,512]
    const float* __restrict__ Wa,         // [64,512]
    const float* __restrict__ Wo,         // [512,1]
    float* __restrict__ out)              // [B]
{
    extern __shared__ float sm[];
    float*  sX    = sm + OFF_X;
    float*  sWt   = sm + OFF_WT;
    __half* sBeta = reinterpret_cast<__half*>(sm + OFF_BETA);
    float*  sWaWo = sm + OFF_WAWO;

    const int tid = threadIdx.x;
    const int tx  = tid & 31;
    const int wid = tid >> 5;
    const int r0  = wid * 4;            // 4 output rows per warp
    const int b0  = blockIdx.x * ROWS;
    const unsigned FULL = 0xffffffffu;

    // ---- stage 0: WaWo[s] = Wa[s,:].Wo  (alpha folded through final dot) ----
#pragma unroll
    for (int si = 0; si < SKUD / 8; si++) {
        int s = wid * 8 + si;
        float p = 0.f;
#pragma unroll
        for (int j = 0; j < 16; j++) {
            int c = tx + 32 * j;
            p = fmaf(__ldg(Wa + s * HID + c), __ldg(Wo + c), p);
        }
#pragma unroll
        for (int o = 16; o > 0; o >>= 1) p += __shfl_xor_sync(FULL, p, o);
        if (tx == 0) sWaWo[s] = p;
    }

    // ---- changepoints via warp shuffle-scan (no shared) ---------------------
    float cps_r[2];
#pragma unroll
    for (int tt = 0; tt < 2; tt++) {
        int h = wid + 8 * tt;
        float d  = deltas[h * C + tx];
        float sp = (d > 20.f) ? d : log1pf(expf(d));
        float s  = sp;
#pragma unroll
        for (int o = 1; o < 32; o <<= 1) {
            float v = __shfl_up_sync(FULL, s, o);
            if (tx >= o) s += v;
        }
        float tot = __shfl_sync(FULL, s, 31);
        cps_r[tt] = s * (TMAX / tot);
    }

    // ---- stage 1: per-(row,holiday) features -> aggregated X ----------------
#pragma unroll
    for (int tt = 0; tt < 2; tt++) {
        int h = wid + 8 * tt;          // warp-uniform
        int r = tx;
        float t = inputs[(size_t)(b0 + r) * H + h];
        float f[C];
        float mu = 0.f;
#pragma unroll
        for (int c = 0; c < C; c++) {
            float cp = __shfl_sync(FULL, cps_r[tt], c);
            f[c] = fmaxf(t - cp, 0.f); mu += f[c];
        }
        mu *= (1.0f / C);
        float var = 0.f;
#pragma unroll
        for (int c = 0; c < C; c++) { float d = f[c] - mu; var = fmaf(d, d, var); }
        var *= (1.0f / C);
        float rs = rsqrtf(var + LN_EPS);
        float aw = __ldg(attn_w + h) * TEMP_INV;
        float m = -3.4e38f;
#pragma unroll
        for (int c = 0; c < C; c++) {
            float n = fmaf((f[c] - mu) * rs, __ldg(ln_gamma + h * C + c),
                           __ldg(ln_beta + h * C + c));
            f[c] = n;
            m = fmaxf(m, n * aw);
        }
        float s = 0.f;
#pragma unroll
        for (int c = 0; c < C; c++) s += expf(f[c] * aw - m);
        float inv = 1.0f / s;

        ull hid2[16];
#pragma unroll
        for (int d = 0; d < 16; d++) hid2[d] = 0ull;
#pragma unroll
        for (int c = 0; c < C; c++) {
            float a = f[c] * expf(f[c] * aw - m) * inv;   // attended
            ull a2 = pack2(a, a);
            const ull* wr = reinterpret_cast<const ull*>(Wh + (h * C + c) * C);
#pragma unroll
            for (int d = 0; d < 16; d++) ffma2(hid2[d], a2, wr[d]);
        }
#pragma unroll
        for (int d = 0; d < 16; d++) {
            float2 hv = unpack2(hid2[d]);
            hv.x = mishf(hv.x); hv.y = mishf(hv.y);
            *reinterpret_cast<float2*>(sX + r * XS + h * 32 + 2 * d) = hv;
        }
    }

    ull acc[4][8];

    // ---- stage 2a: beta = sigmoid(sku @ Wb) -> fp16 shared ------------------
    gemm_acc2(Wb, SKUD, sku + (size_t)b0 * SKUD, SKUD, r0, sWt, acc, tid, tx);
#pragma unroll
    for (int i = 0; i < 4; i++)
#pragma unroll
        for (int j = 0; j < 8; j++) {
            float2 v = unpack2(acc[i][j]);
            v.x = 1.0f / (1.0f + expf(-v.x));
            v.y = 1.0f / (1.0f + expf(-v.y));
            int idx = (r0 + i) * HID + 2 * tx + 64 * j;
            reinterpret_cast<__half2*>(sBeta)[idx >> 1] = __floats2half2_rn(v.x, v.y);
        }

    // ---- stage 2b: H1 = mish(X @ Wah) ---------------------------------------
    gemm_acc2(Wah, HID, sX, XS, r0, sWt, acc, tid, tx);
    // each warp reads/writes only its own X rows -> no barrier needed
#pragma unroll
    for (int i = 0; i < 4; i++)
#pragma unroll
        for (int j = 0; j < 8; j++) {
            float2 v = unpack2(acc[i][j]);
            v.x = mishf(v.x); v.y = mishf(v.y);
            *reinterpret_cast<float2*>(sX + (r0 + i) * XS + 2 * tx + 64 * j) = v;
        }

    // ---- stage 3: logits = H1 @ Waa -----------------------------------------
    gemm_acc2(Waa, HID, sX, XS, r0, sWt, acc, tid, tx);

    // ---- epilogue: softmax, *H1, *beta, +alpha, @Wo -------------------------
#pragma unroll
    for (int i = 0; i < 4; i++) {
        int r = r0 + i;
        float l[16];
        float m = -3.4e38f;
#pragma unroll
        for (int j = 0; j < 8; j++) {
            float2 v = unpack2(acc[i][j]);
            l[2 * j]     = v.x * TEMP_INV;
            l[2 * j + 1] = v.y * TEMP_INV;
            m = fmaxf(m, fmaxf(l[2 * j], l[2 * j + 1]));
        }
#pragma unroll
        for (int o = 16; o > 0; o >>= 1) m = fmaxf(m, __shfl_xor_sync(FULL, m, o));
        float s = 0.f;
#pragma unroll
        for (int j = 0; j < 16; j++) { l[j] = expf(l[j] - m); s += l[j]; }
#pragma unroll
        for (int o = 16; o > 0; o >>= 1) s += __shfl_xor_sync(FULL, s, o);
        float inv = 1.0f / s;

        // alpha contribution: sku[r] . (Wa@Wo)
        float p = fmaf(sku[(size_t)(b0 + r) * SKUD + tx], sWaWo[tx],
                       sku[(size_t)(b0 + r) * SKUD + tx + 32] * sWaWo[tx + 32]);
#pragma unroll
        for (int j = 0; j < 8; j++) {
            int c = 2 * tx + 64 * j;
            float2 h1 = *reinterpret_cast<const float2*>(sX + r * XS + c);
            float2 bt = __half22float2(
                reinterpret_cast<const __half2*>(sBeta)[(r * HID + c) >> 1]);
            float2 wo = *reinterpret_cast<const float2*>(Wo + c);
            p = fmaf(h1.x * (l[2 * j] * inv) * bt.x, wo.x, p);
            p = fmaf(h1.y * (l[2 * j + 1] * inv) * bt.y, wo.y, p);
        }
#pragma unroll
        for (int o = 16; o > 0; o >>= 1) p += __shfl_xor_sync(FULL, p, o);
        if (tx == 0) out[b0 + r] = p;
    }
}

extern "C" void kernel_launch(void* const* d_in, const int* in_sizes, int n_in,
                              void* d_out, int out_size)
{
    const float* inputs   = (const float*)d_in[0];
    const float* sku      = (const float*)d_in[1];
    const float* deltas   = (const float*)d_in[2];
    const float* ln_gamma = (const float*)d_in[3];
    const float* ln_beta  = (const float*)d_in[4];
    const float* attn_w   = (const float*)d_in[5];
    const float* Wh       = (const float*)d_in[6];
    const float* Wah      = (const float*)d_in[7];
    const float* Waa      = (const float*)d_in[8];
    const float* Wb       = (const float*)d_in[9];
    const float* Wa       = (const float*)d_in[10];
    const float* Wo       = (const float*)d_in[11];
    float* out = (float*)d_out;

    int B = in_sizes[0] / H;
    cudaFuncSetAttribute(holiday_fused_kernel,
                         cudaFuncAttributeMaxDynamicSharedMemorySize, SMEM_BYTES);
    holiday_fused_kernel<<<B / ROWS, NTHR, SMEM_BYTES>>>(
        inputs, sku, deltas, ln_gamma, ln_beta, attn_w,
        Wh, Wah, Waa, Wb, Wa, Wo, out);
}